// round 3
// baseline (speedup 1.0000x reference)
#include <cuda_runtime.h>
#include <cuda_bf16.h>
#include <math.h>

#define SQ   1024
#define DM   2048
#define NH   32
#define HD   64
#define NBLK 16
#define NE   4
#define DF   8192
#define VOC  50257

// ---------------- scratch (device globals; no dynamic allocation) ----------------
__device__ float g_x  [SQ*DM];   // embeddings / residual
__device__ float g_q  [SQ*DM];
__device__ float g_k  [SQ*DM];
__device__ float g_v  [SQ*DM];
__device__ float g_att[SQ*DM];
__device__ float g_x1 [SQ*DM];   // attn + residual
__device__ float g_x2 [SQ*DM];   // after ln1 (MoE input)
__device__ float g_x3 [SQ*DM];   // after ln2+fin
__device__ float g_cos[SQ*HD/2];
__device__ float g_sin[SQ*HD/2];
__device__ int   g_cnt[NE];
__device__ int   g_etok[NE*SQ];
__device__ int   g_tok_slot[SQ*2];
__device__ float g_tok_w  [SQ*2];
__device__ float g_h1[33554432];  // NE*SQ*DF
__device__ float g_h3[33554432];
__device__ float g_y [8388608];   // NE*SQ*DM
__device__ float g_aux;

// ---------------- small helpers ----------------
__device__ __forceinline__ float block_sum_256(float v, float* sm) {
    __syncthreads();
    #pragma unroll
    for (int o = 16; o > 0; o >>= 1) v += __shfl_down_sync(0xffffffffu, v, o);
    if ((threadIdx.x & 31) == 0) sm[threadIdx.x >> 5] = v;
    __syncthreads();
    float r = 0.f;
    if (threadIdx.x < 8) {
        r = sm[threadIdx.x];
        #pragma unroll
        for (int o = 4; o > 0; o >>= 1) r += __shfl_down_sync(0x000000ffu, r, o);
        if (threadIdx.x == 0) sm[0] = r;
    }
    __syncthreads();
    return sm[0];
}

// ---------------- rope tables ----------------
__global__ void ropetab_k() {
    int s = blockIdx.x, i = threadIdx.x;                  // i in [0,32)
    double inv = exp(-((double)(2 * i) / 64.0) * log(10000.0));
    double ang = (double)s * inv;
    g_cos[s * 32 + i] = (float)cos(ang);
    g_sin[s * 32 + i] = (float)sin(ang);
}

// ---------------- embedding gather ----------------
__global__ void embed_k(const int* __restrict__ tok, const float* __restrict__ emb) {
    int t = blockIdx.x;
    int row = tok[t];
    const float4* src = (const float4*)(emb + (size_t)row * DM);
    float4* dst = (float4*)(g_x + (size_t)t * DM);
    for (int i = threadIdx.x; i < DM / 4; i += blockDim.x) dst[i] = src[i];
}

// ---------------- rope apply (in place on q,k) ----------------
__global__ void rope_k() {
    int s = blockIdx.x;
    int idx = threadIdx.x;                // 1024 = 32 heads * 32 pairs
    int h = idx >> 5, i = idx & 31;
    float c = g_cos[s * 32 + i], sn = g_sin[s * 32 + i];
    size_t base = (size_t)s * DM + h * 64 + 2 * i;
    float q0 = g_q[base], q1 = g_q[base + 1];
    g_q[base]     = q0 * c - q1 * sn;
    g_q[base + 1] = q0 * sn + q1 * c;
    float k0 = g_k[base], k1 = g_k[base + 1];
    g_k[base]     = k0 * c - k1 * sn;
    g_k[base + 1] = k0 * sn + k1 * c;
}

// ---------------- generic 128x128x16 fp32 GEMM core: C[m][n] = sum_k A[m][k]*B[n][k] ----------------
__device__ __forceinline__ void gemm_core(
    const float* __restrict__ A, const int* __restrict__ gather,
    const float* __restrict__ B, float* __restrict__ C,
    int M, int N, int K, const float* __restrict__ Res,
    int m0, int n0)
{
    __shared__ float As[16 * 128];
    __shared__ float Bs[16 * 128];
    __shared__ int   rowidx[128];
    int tid = threadIdx.x;
    if (tid < 128) {
        int m = m0 + tid;
        rowidx[tid] = (m < M) ? (gather ? gather[m] : m) : -1;
    }
    __syncthreads();
    int lr = tid >> 1;
    int lc = (tid & 1) * 8;
    int tx = tid & 15;
    int ty = tid >> 4;

    float acc[8][8];
    #pragma unroll
    for (int u = 0; u < 8; u++)
        #pragma unroll
        for (int v = 0; v < 8; v++) acc[u][v] = 0.f;

    int ri = rowidx[lr];
    bool aval = (ri >= 0);
    const float* Arow = aval ? (A + (size_t)ri * K) : A;
    int bn = n0 + lr;
    bool bval = (bn < N);
    const float* Brow = bval ? (B + (size_t)bn * K) : B;

    for (int k0 = 0; k0 < K; k0 += 16) {
        float4 a0 = aval ? *(const float4*)(Arow + k0 + lc)     : make_float4(0, 0, 0, 0);
        float4 a1 = aval ? *(const float4*)(Arow + k0 + lc + 4) : make_float4(0, 0, 0, 0);
        float4 b0 = bval ? *(const float4*)(Brow + k0 + lc)     : make_float4(0, 0, 0, 0);
        float4 b1 = bval ? *(const float4*)(Brow + k0 + lc + 4) : make_float4(0, 0, 0, 0);
        __syncthreads();
        As[(lc + 0) * 128 + lr] = a0.x; As[(lc + 1) * 128 + lr] = a0.y;
        As[(lc + 2) * 128 + lr] = a0.z; As[(lc + 3) * 128 + lr] = a0.w;
        As[(lc + 4) * 128 + lr] = a1.x; As[(lc + 5) * 128 + lr] = a1.y;
        As[(lc + 6) * 128 + lr] = a1.z; As[(lc + 7) * 128 + lr] = a1.w;
        Bs[(lc + 0) * 128 + lr] = b0.x; Bs[(lc + 1) * 128 + lr] = b0.y;
        Bs[(lc + 2) * 128 + lr] = b0.z; Bs[(lc + 3) * 128 + lr] = b0.w;
        Bs[(lc + 4) * 128 + lr] = b1.x; Bs[(lc + 5) * 128 + lr] = b1.y;
        Bs[(lc + 6) * 128 + lr] = b1.z; Bs[(lc + 7) * 128 + lr] = b1.w;
        __syncthreads();
        #pragma unroll
        for (int kk = 0; kk < 16; kk++) {
            float av[8], bv[8];
            *(float4*)&av[0] = *(const float4*)&As[kk * 128 + ty * 8];
            *(float4*)&av[4] = *(const float4*)&As[kk * 128 + ty * 8 + 4];
            *(float4*)&bv[0] = *(const float4*)&Bs[kk * 128 + tx * 8];
            *(float4*)&bv[4] = *(const float4*)&Bs[kk * 128 + tx * 8 + 4];
            #pragma unroll
            for (int u = 0; u < 8; u++)
                #pragma unroll
                for (int v = 0; v < 8; v++) acc[u][v] += av[u] * bv[v];
        }
    }
    #pragma unroll
    for (int u = 0; u < 8; u++) {
        int m = m0 + ty * 8 + u;
        if (m >= M) continue;
        #pragma unroll
        for (int v = 0; v < 8; v++) {
            int n = n0 + tx * 8 + v;
            if (n >= N) continue;
            float val = acc[u][v];
            if (Res) val += Res[(size_t)m * N + n];
            C[(size_t)m * N + n] = val;
        }
    }
}

__global__ void gemm_plain(const float* __restrict__ A, const float* __restrict__ B,
                           float* __restrict__ C, int M, int N, int K,
                           const float* __restrict__ Res) {
    gemm_core(A, nullptr, B, C, M, N, K, Res, blockIdx.y * 128, blockIdx.x * 128);
}

__global__ void moe_gemm_in(const float* __restrict__ X, const float* __restrict__ W,
                            float* __restrict__ Hout) {
    int e = blockIdx.z;
    int cnt = g_cnt[e];
    int m0 = blockIdx.y * 128;
    if (m0 >= cnt) return;
    gemm_core(X, g_etok + e * SQ, W + (size_t)e * DF * DM,
              Hout + (size_t)e * SQ * DF, cnt, DF, DM, nullptr, m0, blockIdx.x * 128);
}

__global__ void moe_gemm_out(const float* __restrict__ Hin, const float* __restrict__ W2,
                             float* __restrict__ Y) {
    int e = blockIdx.z;
    int cnt = g_cnt[e];
    int m0 = blockIdx.y * 128;
    if (m0 >= cnt) return;
    gemm_core(Hin + (size_t)e * SQ * DF, nullptr, W2 + (size_t)e * DM * DF,
              Y + (size_t)e * SQ * DM, cnt, DM, DF, nullptr, m0, blockIdx.x * 128);
}

// ---------------- block-tiled attention (replicates reference per-block max semantics) ----------------
__global__ void attn_k() {
    int h  = blockIdx.x;
    int ib = blockIdx.y;
    __shared__ float Qs[64 * 64];
    __shared__ float KV[64 * 64];
    __shared__ float SC[64 * 64];
    int tid = threadIdx.x;            // 256
    int tx = tid & 15, ty = tid >> 4;

    for (int idx = tid; idx < 64 * 16; idx += 256) {
        int r = idx >> 4, c4 = (idx & 15) * 4;
        *(float4*)&Qs[r * 64 + c4] =
            *(const float4*)&g_q[(size_t)(ib * 64 + r) * DM + h * 64 + c4];
    }

    float acc[4][4];
    #pragma unroll
    for (int u = 0; u < 4; u++)
        #pragma unroll
        for (int v = 0; v < 4; v++) acc[u][v] = 0.f;
    float Lacc = 0.f;

    for (int j = 0; j <= ib; j++) {
        __syncthreads();
        // K block, transposed: KV[c*64 + r] = K[j*64+r][h*64+c]
        for (int idx = tid; idx < 1024; idx += 256) {
            int r = idx >> 4, c4 = (idx & 15) * 4;
            float4 kv = *(const float4*)&g_k[(size_t)(j * 64 + r) * DM + h * 64 + c4];
            KV[(c4 + 0) * 64 + r] = kv.x;
            KV[(c4 + 1) * 64 + r] = kv.y;
            KV[(c4 + 2) * 64 + r] = kv.z;
            KV[(c4 + 3) * 64 + r] = kv.w;
        }
        __syncthreads();
        // scores = Q @ K^T * scale
        {
            float sc[4][4];
            #pragma unroll
            for (int u = 0; u < 4; u++)
                #pragma unroll
                for (int v = 0; v < 4; v++) sc[u][v] = 0.f;
            for (int kk = 0; kk < 64; kk++) {
                float qv[4], kvv[4];
                #pragma unroll
                for (int u = 0; u < 4; u++) qv[u] = Qs[(ty * 4 + u) * 64 + kk];
                #pragma unroll
                for (int v = 0; v < 4; v++) kvv[v] = KV[kk * 64 + tx * 4 + v];
                #pragma unroll
                for (int u = 0; u < 4; u++)
                    #pragma unroll
                    for (int v = 0; v < 4; v++) sc[u][v] += qv[u] * kvv[v];
            }
            #pragma unroll
            for (int u = 0; u < 4; u++)
                #pragma unroll
                for (int v = 0; v < 4; v++)
                    SC[(ty * 4 + u) * 64 + tx * 4 + v] = sc[u][v] * 0.125f;
        }
        __syncthreads();
        // per-row (within this 64-key block): max, exp, sum; causal mask on diag block
        if (tid < 64) {
            int r = tid;
            int kmax = (j == ib) ? r : 63;
            float m = -1e30f;
            for (int kk = 0; kk <= kmax; kk++) m = fmaxf(m, SC[r * 64 + kk]);
            float ssum = 0.f;
            for (int kk = 0; kk < 64; kk++) {
                float p = (kk <= kmax) ? __expf(SC[r * 64 + kk] - m) : 0.f;
                SC[r * 64 + kk] = p;
                ssum += p;
            }
            Lacc += ssum;
        }
        __syncthreads();
        // V block (row-major)
        for (int idx = tid; idx < 1024; idx += 256) {
            int r = idx >> 4, c4 = (idx & 15) * 4;
            *(float4*)&KV[r * 64 + c4] =
                *(const float4*)&g_v[(size_t)(j * 64 + r) * DM + h * 64 + c4];
        }
        __syncthreads();
        // O += P @ V
        for (int kk = 0; kk < 64; kk++) {
            float pv[4], vv[4];
            #pragma unroll
            for (int u = 0; u < 4; u++) pv[u] = SC[(ty * 4 + u) * 64 + kk];
            #pragma unroll
            for (int v = 0; v < 4; v++) vv[v] = KV[kk * 64 + tx * 4 + v];
            #pragma unroll
            for (int u = 0; u < 4; u++)
                #pragma unroll
                for (int v = 0; v < 4; v++) acc[u][v] += pv[u] * vv[v];
        }
    }
    __syncthreads();
    if (tid < 64) SC[tid] = Lacc;
    __syncthreads();
    #pragma unroll
    for (int u = 0; u < 4; u++) {
        int r = ty * 4 + u;
        float invl = 1.f / (SC[r] + 1e-6f);
        #pragma unroll
        for (int v = 0; v < 4; v++)
            g_att[(size_t)(ib * 64 + r) * DM + h * 64 + tx * 4 + v] = acc[u][v] * invl;
    }
}

// ---------------- layernorm ----------------
__global__ void layernorm_k(const float* __restrict__ X, const float* __restrict__ g,
                            const float* __restrict__ b, float* __restrict__ Y) {
    int t = blockIdx.x;
    __shared__ float sm[8];
    const float* x = X + (size_t)t * DM;
    float loc[8];
    float s = 0.f, ss = 0.f;
    #pragma unroll
    for (int i = 0; i < 8; i++) {
        float v = x[threadIdx.x + i * 256];
        loc[i] = v; s += v; ss += v * v;
    }
    s  = block_sum_256(s, sm);
    ss = block_sum_256(ss, sm);
    float mu  = s * (1.f / DM);
    float var = ss * (1.f / DM) - mu * mu;
    float inv = rsqrtf(var + 1e-5f);
    float* y = Y + (size_t)t * DM;
    #pragma unroll
    for (int i = 0; i < 8; i++) {
        int d = threadIdx.x + i * 256;
        y[d] = (loc[i] - mu) * inv * g[d] + b[d];
    }
}

// ---------------- moe bookkeeping ----------------
__global__ void init_moe_k() {
    if (threadIdx.x < NE) g_cnt[threadIdx.x] = 0;
    if (threadIdx.x == NE) g_aux = 0.f;
}

__global__ void gate_k(const float* __restrict__ X2, const float* __restrict__ GW) {
    int t = blockIdx.x;                 // 128 threads
    __shared__ float sm[4][4];
    float p0 = 0.f, p1 = 0.f, p2 = 0.f, p3 = 0.f;
    for (int d = threadIdx.x; d < DM; d += 128) {
        float xv = X2[(size_t)t * DM + d];
        p0 += xv * GW[0 * DM + d];
        p1 += xv * GW[1 * DM + d];
        p2 += xv * GW[2 * DM + d];
        p3 += xv * GW[3 * DM + d];
    }
    #pragma unroll
    for (int o = 16; o > 0; o >>= 1) {
        p0 += __shfl_down_sync(0xffffffffu, p0, o);
        p1 += __shfl_down_sync(0xffffffffu, p1, o);
        p2 += __shfl_down_sync(0xffffffffu, p2, o);
        p3 += __shfl_down_sync(0xffffffffu, p3, o);
    }
    int w = threadIdx.x >> 5;
    if ((threadIdx.x & 31) == 0) {
        sm[w][0] = p0; sm[w][1] = p1; sm[w][2] = p2; sm[w][3] = p3;
    }
    __syncthreads();
    if (threadIdx.x == 0) {
        float l[4];
        #pragma unroll
        for (int e = 0; e < 4; e++) l[e] = sm[0][e] + sm[1][e] + sm[2][e] + sm[3][e];
        float mean = (l[0] + l[1] + l[2] + l[3]) * 0.25f;
        float var = 0.f;
        #pragma unroll
        for (int e = 0; e < 4; e++) var += (l[e] - mean) * (l[e] - mean);
        var *= (1.f / 3.f);                           // ddof=1
        atomicAdd(&g_aux, var * (1.f / SQ));
        float m = fmaxf(fmaxf(l[0], l[1]), fmaxf(l[2], l[3]));
        float pe[4]; float Z = 0.f;
        #pragma unroll
        for (int e = 0; e < 4; e++) { pe[e] = expf(l[e] - m); Z += pe[e]; }
        #pragma unroll
        for (int e = 0; e < 4; e++) pe[e] /= Z;
        int i1 = 0;
        for (int e = 1; e < 4; e++) if (pe[e] > pe[i1]) i1 = e;
        int i2 = -1;
        for (int e = 0; e < 4; e++) if (e != i1 && (i2 < 0 || pe[e] > pe[i2])) i2 = e;
        float den = pe[i1] + pe[i2];
        int s0 = atomicAdd(&g_cnt[i1], 1);
        g_etok[i1 * SQ + s0] = t;
        g_tok_slot[2 * t] = i1 * SQ + s0;
        g_tok_w[2 * t] = pe[i1] / den;
        int s1 = atomicAdd(&g_cnt[i2], 1);
        g_etok[i2 * SQ + s1] = t;
        g_tok_slot[2 * t + 1] = i2 * SQ + s1;
        g_tok_w[2 * t + 1] = pe[i2] / den;
    }
}

__global__ void silu_mul_k() {
    int row = blockIdx.x;               // NE*SQ rows
    int e = row >> 10;
    int slot = row & 1023;
    if (slot >= g_cnt[e]) return;
    size_t base = (size_t)row * DF;
    for (int f = threadIdx.x; f < DF; f += blockDim.x) {
        float h1 = g_h1[base + f], h3 = g_h3[base + f];
        g_h1[base + f] = h1 / (1.f + __expf(-h1)) * h3;
    }
}

// ---------------- combine moe + residual + ln2 + fin-ln ----------------
__global__ void combine_ln_k(const float* __restrict__ Y, const float* __restrict__ X2,
                             const float* __restrict__ ln2g, const float* __restrict__ ln2b,
                             const float* __restrict__ fing, const float* __restrict__ finb,
                             float* __restrict__ Out) {
    int t = blockIdx.x;
    __shared__ float sm[8];
    int f0 = g_tok_slot[t * 2], f1 = g_tok_slot[t * 2 + 1];
    float w0 = g_tok_w[t * 2], w1 = g_tok_w[t * 2 + 1];
    const float* y0 = Y + (size_t)f0 * DM;
    const float* y1 = Y + (size_t)f1 * DM;
    float loc[8];
    float s = 0.f, ss = 0.f;
    #pragma unroll
    for (int i = 0; i < 8; i++) {
        int d = threadIdx.x + i * 256;
        float a = w0 * y0[d] + w1 * y1[d] + X2[(size_t)t * DM + d];
        loc[i] = a; s += a; ss += a * a;
    }
    s  = block_sum_256(s, sm);
    ss = block_sum_256(ss, sm);
    float mu  = s * (1.f / DM);
    float var = ss * (1.f / DM) - mu * mu;
    float inv = rsqrtf(var + 1e-5f);
    float s2 = 0.f, ss2 = 0.f;
    #pragma unroll
    for (int i = 0; i < 8; i++) {
        int d = threadIdx.x + i * 256;
        float bn = (loc[i] - mu) * inv * ln2g[d] + ln2b[d];
        loc[i] = bn; s2 += bn; ss2 += bn * bn;
    }
    s2  = block_sum_256(s2, sm);
    ss2 = block_sum_256(ss2, sm);
    float mu2  = s2 * (1.f / DM);
    float var2 = ss2 * (1.f / DM) - mu2 * mu2;
    float inv2 = rsqrtf(var2 + 1e-5f);
    #pragma unroll
    for (int i = 0; i < 8; i++) {
        int d = threadIdx.x + i * 256;
        Out[(size_t)t * DM + d] = (loc[i] - mu2) * inv2 * fing[d] + finb[d];
    }
}

__global__ void aux_write_k(float* out, int out_size) {
    if (out_size > SQ * VOC) out[(size_t)SQ * VOC] = g_aux;
}

// ---------------- launch ----------------
extern "C" void kernel_launch(void* const* d_in, const int* in_sizes, int n_in,
                              void* d_out, int out_size) {
    const int*   tokens = (const int*)d_in[0];
    const float* emb    = (const float*)d_in[1];
    const float* wq     = (const float*)d_in[2];
    const float* wk     = (const float*)d_in[3];
    const float* wv     = (const float*)d_in[4];
    const float* wo     = (const float*)d_in[5];
    const float* ln1_g  = (const float*)d_in[6];
    const float* ln1_b  = (const float*)d_in[7];
    const float* gate_w = (const float*)d_in[8];
    const float* w1     = (const float*)d_in[9];
    const float* w2     = (const float*)d_in[10];
    const float* w3     = (const float*)d_in[11];
    const float* ln2_g  = (const float*)d_in[12];
    const float* ln2_b  = (const float*)d_in[13];
    const float* fin_g  = (const float*)d_in[14];
    const float* fin_b  = (const float*)d_in[15];
    const float* head_w = (const float*)d_in[16];
    float* out = (float*)d_out;

    float *p_x, *p_q, *p_k, *p_v, *p_att, *p_x1, *p_x2, *p_x3, *p_h1, *p_h3, *p_y;
    cudaGetSymbolAddress((void**)&p_x,  g_x);
    cudaGetSymbolAddress((void**)&p_q,  g_q);
    cudaGetSymbolAddress((void**)&p_k,  g_k);
    cudaGetSymbolAddress((void**)&p_v,  g_v);
    cudaGetSymbolAddress((void**)&p_att, g_att);
    cudaGetSymbolAddress((void**)&p_x1, g_x1);
    cudaGetSymbolAddress((void**)&p_x2, g_x2);
    cudaGetSymbolAddress((void**)&p_x3, g_x3);
    cudaGetSymbolAddress((void**)&p_h1, g_h1);
    cudaGetSymbolAddress((void**)&p_h3, g_h3);
    cudaGetSymbolAddress((void**)&p_y,  g_y);

    ropetab_k<<<SQ, 32>>>();
    embed_k<<<SQ, 256>>>(tokens, emb);

    gemm_plain<<<dim3(DM / 128, SQ / 128), 256>>>(p_x, wq, p_q, SQ, DM, DM, nullptr);
    gemm_plain<<<dim3(DM / 128, SQ / 128), 256>>>(p_x, wk, p_k, SQ, DM, DM, nullptr);
    gemm_plain<<<dim3(DM / 128, SQ / 128), 256>>>(p_x, wv, p_v, SQ, DM, DM, nullptr);

    rope_k<<<SQ, 1024>>>();
    attn_k<<<dim3(NH, NBLK), 256>>>();

    gemm_plain<<<dim3(DM / 128, SQ / 128), 256>>>(p_att, wo, p_x1, SQ, DM, DM, p_x);
    layernorm_k<<<SQ, 256>>>(p_x1, ln1_g, ln1_b, p_x2);

    init_moe_k<<<1, 32>>>();
    gate_k<<<SQ, 128>>>(p_x2, gate_w);

    moe_gemm_in<<<dim3(DF / 128, SQ / 128, NE), 256>>>(p_x2, w1, p_h1);
    moe_gemm_in<<<dim3(DF / 128, SQ / 128, NE), 256>>>(p_x2, w3, p_h3);
    silu_mul_k<<<NE * SQ, 256>>>();
    moe_gemm_out<<<dim3(DM / 128, SQ / 128, NE), 256>>>(p_h1, w2, p_y);

    combine_ln_k<<<SQ, 256>>>(p_y, p_x2, ln2_g, ln2_b, fin_g, fin_b, p_x3);

    gemm_plain<<<dim3((VOC + 127) / 128, SQ / 128), 256>>>(p_x3, head_w, out, SQ, VOC, DM, nullptr);
    aux_write_k<<<1, 1>>>(out, out_size);
}

// round 4
// speedup vs baseline: 1.0027x; 1.0027x over previous
#include <cuda_runtime.h>
#include <cuda_bf16.h>
#include <math.h>

#define SQ   1024
#define DM   2048
#define NH   32
#define HD   64
#define NBLK 16
#define NE   4
#define DF   8192
#define VOC  50257

// ---------------- scratch (device globals; no dynamic allocation) ----------------
__device__ float g_x  [SQ*DM];   // embeddings / residual
__device__ float g_q  [SQ*DM];
__device__ float g_k  [SQ*DM];
__device__ float g_v  [SQ*DM];
__device__ float g_att[SQ*DM];
__device__ float g_x1 [SQ*DM];   // attn + residual
__device__ float g_x2 [SQ*DM];   // after ln1 (MoE input)
__device__ float g_x3 [SQ*DM];   // after ln2+fin
__device__ float g_cos[SQ*HD/2];
__device__ float g_sin[SQ*HD/2];
__device__ int   g_cnt[NE];
__device__ int   g_etok[NE*SQ];
__device__ int   g_tok_slot[SQ*2];
__device__ float g_tok_w  [SQ*2];
__device__ float g_h1[33554432];  // NE*SQ*DF
__device__ float g_h3[33554432];
__device__ float g_y [8388608];   // NE*SQ*DM
__device__ float g_aux;

// ---------------- small helpers ----------------
__device__ __forceinline__ float block_sum_256(float v, float* sm) {
    __syncthreads();
    #pragma unroll
    for (int o = 16; o > 0; o >>= 1) v += __shfl_down_sync(0xffffffffu, v, o);
    if ((threadIdx.x & 31) == 0) sm[threadIdx.x >> 5] = v;
    __syncthreads();
    float r = 0.f;
    if (threadIdx.x < 8) {
        r = sm[threadIdx.x];
        #pragma unroll
        for (int o = 4; o > 0; o >>= 1) r += __shfl_down_sync(0x000000ffu, r, o);
        if (threadIdx.x == 0) sm[0] = r;
    }
    __syncthreads();
    return sm[0];
}

// ---------------- rope tables ----------------
__global__ void ropetab_k() {
    int s = blockIdx.x, i = threadIdx.x;                  // i in [0,32)
    double inv = exp(-((double)(2 * i) / 64.0) * log(10000.0));
    double ang = (double)s * inv;
    g_cos[s * 32 + i] = (float)cos(ang);
    g_sin[s * 32 + i] = (float)sin(ang);
}

// ---------------- embedding gather ----------------
__global__ void embed_k(const int* __restrict__ tok, const float* __restrict__ emb) {
    int t = blockIdx.x;
    int row = tok[t];
    const float4* src = (const float4*)(emb + (size_t)row * DM);
    float4* dst = (float4*)(g_x + (size_t)t * DM);
    for (int i = threadIdx.x; i < DM / 4; i += blockDim.x) dst[i] = src[i];
}

// ---------------- rope apply (in place on q,k) ----------------
__global__ void rope_k() {
    int s = blockIdx.x;
    int idx = threadIdx.x;                // 1024 = 32 heads * 32 pairs
    int h = idx >> 5, i = idx & 31;
    float c = g_cos[s * 32 + i], sn = g_sin[s * 32 + i];
    size_t base = (size_t)s * DM + h * 64 + 2 * i;
    float q0 = g_q[base], q1 = g_q[base + 1];
    g_q[base]     = q0 * c - q1 * sn;
    g_q[base + 1] = q0 * sn + q1 * c;
    float k0 = g_k[base], k1 = g_k[base + 1];
    g_k[base]     = k0 * c - k1 * sn;
    g_k[base + 1] = k0 * sn + k1 * c;
}

// ---------------- generic 128x128x16 fp32 GEMM core: C[m][n] = sum_k A[m][k]*B[n][k] ----------------
__device__ __forceinline__ void gemm_core(
    const float* __restrict__ A, const int* __restrict__ gather,
    const float* __restrict__ B, float* __restrict__ C,
    int M, int N, int K, const float* __restrict__ Res,
    int m0, int n0)
{
    __shared__ float As[16 * 128];
    __shared__ float Bs[16 * 128];
    __shared__ int   rowidx[128];
    int tid = threadIdx.x;
    if (tid < 128) {
        int m = m0 + tid;
        rowidx[tid] = (m < M) ? (gather ? gather[m] : m) : -1;
    }
    __syncthreads();
    int lr = tid >> 1;
    int lc = (tid & 1) * 8;
    int tx = tid & 15;
    int ty = tid >> 4;

    float acc[8][8];
    #pragma unroll
    for (int u = 0; u < 8; u++)
        #pragma unroll
        for (int v = 0; v < 8; v++) acc[u][v] = 0.f;

    int ri = rowidx[lr];
    bool aval = (ri >= 0);
    const float* Arow = aval ? (A + (size_t)ri * K) : A;
    int bn = n0 + lr;
    bool bval = (bn < N);
    const float* Brow = bval ? (B + (size_t)bn * K) : B;

    for (int k0 = 0; k0 < K; k0 += 16) {
        float4 a0 = aval ? *(const float4*)(Arow + k0 + lc)     : make_float4(0, 0, 0, 0);
        float4 a1 = aval ? *(const float4*)(Arow + k0 + lc + 4) : make_float4(0, 0, 0, 0);
        float4 b0 = bval ? *(const float4*)(Brow + k0 + lc)     : make_float4(0, 0, 0, 0);
        float4 b1 = bval ? *(const float4*)(Brow + k0 + lc + 4) : make_float4(0, 0, 0, 0);
        __syncthreads();
        As[(lc + 0) * 128 + lr] = a0.x; As[(lc + 1) * 128 + lr] = a0.y;
        As[(lc + 2) * 128 + lr] = a0.z; As[(lc + 3) * 128 + lr] = a0.w;
        As[(lc + 4) * 128 + lr] = a1.x; As[(lc + 5) * 128 + lr] = a1.y;
        As[(lc + 6) * 128 + lr] = a1.z; As[(lc + 7) * 128 + lr] = a1.w;
        Bs[(lc + 0) * 128 + lr] = b0.x; Bs[(lc + 1) * 128 + lr] = b0.y;
        Bs[(lc + 2) * 128 + lr] = b0.z; Bs[(lc + 3) * 128 + lr] = b0.w;
        Bs[(lc + 4) * 128 + lr] = b1.x; Bs[(lc + 5) * 128 + lr] = b1.y;
        Bs[(lc + 6) * 128 + lr] = b1.z; Bs[(lc + 7) * 128 + lr] = b1.w;
        __syncthreads();
        #pragma unroll
        for (int kk = 0; kk < 16; kk++) {
            float av[8], bv[8];
            *(float4*)&av[0] = *(const float4*)&As[kk * 128 + ty * 8];
            *(float4*)&av[4] = *(const float4*)&As[kk * 128 + ty * 8 + 4];
            *(float4*)&bv[0] = *(const float4*)&Bs[kk * 128 + tx * 8];
            *(float4*)&bv[4] = *(const float4*)&Bs[kk * 128 + tx * 8 + 4];
            #pragma unroll
            for (int u = 0; u < 8; u++)
                #pragma unroll
                for (int v = 0; v < 8; v++) acc[u][v] += av[u] * bv[v];
        }
    }
    #pragma unroll
    for (int u = 0; u < 8; u++) {
        int m = m0 + ty * 8 + u;
        if (m >= M) continue;
        #pragma unroll
        for (int v = 0; v < 8; v++) {
            int n = n0 + tx * 8 + v;
            if (n >= N) continue;
            float val = acc[u][v];
            if (Res) val += Res[(size_t)m * N + n];
            C[(size_t)m * N + n] = val;
        }
    }
}

__global__ void gemm_plain(const float* __restrict__ A, const float* __restrict__ B,
                           float* __restrict__ C, int M, int N, int K,
                           const float* __restrict__ Res) {
    gemm_core(A, nullptr, B, C, M, N, K, Res, blockIdx.y * 128, blockIdx.x * 128);
}

__global__ void moe_gemm_in(const float* __restrict__ X, const float* __restrict__ W,
                            float* __restrict__ Hout) {
    int e = blockIdx.z;
    int cnt = g_cnt[e];
    int m0 = blockIdx.y * 128;
    if (m0 >= cnt) return;
    gemm_core(X, g_etok + e * SQ, W + (size_t)e * DF * DM,
              Hout + (size_t)e * SQ * DF, cnt, DF, DM, nullptr, m0, blockIdx.x * 128);
}

__global__ void moe_gemm_out(const float* __restrict__ Hin, const float* __restrict__ W2,
                             float* __restrict__ Y) {
    int e = blockIdx.z;
    int cnt = g_cnt[e];
    int m0 = blockIdx.y * 128;
    if (m0 >= cnt) return;
    gemm_core(Hin + (size_t)e * SQ * DF, nullptr, W2 + (size_t)e * DM * DF,
              Y + (size_t)e * SQ * DM, cnt, DM, DF, nullptr, m0, blockIdx.x * 128);
}

// ---------------- block-tiled attention (replicates reference per-block max semantics) ----------------
__global__ void attn_k() {
    int h  = blockIdx.x;
    int ib = blockIdx.y;
    __shared__ float Qs[64 * 64];
    __shared__ float KV[64 * 64];
    __shared__ float SC[64 * 64];
    int tid = threadIdx.x;            // 256
    int tx = tid & 15, ty = tid >> 4;

    for (int idx = tid; idx < 64 * 16; idx += 256) {
        int r = idx >> 4, c4 = (idx & 15) * 4;
        *(float4*)&Qs[r * 64 + c4] =
            *(const float4*)&g_q[(size_t)(ib * 64 + r) * DM + h * 64 + c4];
    }

    float acc[4][4];
    #pragma unroll
    for (int u = 0; u < 4; u++)
        #pragma unroll
        for (int v = 0; v < 4; v++) acc[u][v] = 0.f;
    float Lacc = 0.f;

    for (int j = 0; j <= ib; j++) {
        __syncthreads();
        // K block, transposed: KV[c*64 + r] = K[j*64+r][h*64+c]
        for (int idx = tid; idx < 1024; idx += 256) {
            int r = idx >> 4, c4 = (idx & 15) * 4;
            float4 kv = *(const float4*)&g_k[(size_t)(j * 64 + r) * DM + h * 64 + c4];
            KV[(c4 + 0) * 64 + r] = kv.x;
            KV[(c4 + 1) * 64 + r] = kv.y;
            KV[(c4 + 2) * 64 + r] = kv.z;
            KV[(c4 + 3) * 64 + r] = kv.w;
        }
        __syncthreads();
        // scores = Q @ K^T * scale
        {
            float sc[4][4];
            #pragma unroll
            for (int u = 0; u < 4; u++)
                #pragma unroll
                for (int v = 0; v < 4; v++) sc[u][v] = 0.f;
            for (int kk = 0; kk < 64; kk++) {
                float qv[4], kvv[4];
                #pragma unroll
                for (int u = 0; u < 4; u++) qv[u] = Qs[(ty * 4 + u) * 64 + kk];
                #pragma unroll
                for (int v = 0; v < 4; v++) kvv[v] = KV[kk * 64 + tx * 4 + v];
                #pragma unroll
                for (int u = 0; u < 4; u++)
                    #pragma unroll
                    for (int v = 0; v < 4; v++) sc[u][v] += qv[u] * kvv[v];
            }
            #pragma unroll
            for (int u = 0; u < 4; u++)
                #pragma unroll
                for (int v = 0; v < 4; v++)
                    SC[(ty * 4 + u) * 64 + tx * 4 + v] = sc[u][v] * 0.125f;
        }
        __syncthreads();
        // per-row (within this 64-key block): max, exp, sum; causal mask on diag block
        if (tid < 64) {
            int r = tid;
            int kmax = (j == ib) ? r : 63;
            float m = -1e30f;
            for (int kk = 0; kk <= kmax; kk++) m = fmaxf(m, SC[r * 64 + kk]);
            float ssum = 0.f;
            for (int kk = 0; kk < 64; kk++) {
                float p = (kk <= kmax) ? __expf(SC[r * 64 + kk] - m) : 0.f;
                SC[r * 64 + kk] = p;
                ssum += p;
            }
            Lacc += ssum;
        }
        __syncthreads();
        // V block (row-major)
        for (int idx = tid; idx < 1024; idx += 256) {
            int r = idx >> 4, c4 = (idx & 15) * 4;
            *(float4*)&KV[r * 64 + c4] =
                *(const float4*)&g_v[(size_t)(j * 64 + r) * DM + h * 64 + c4];
        }
        __syncthreads();
        // O += P @ V
        for (int kk = 0; kk < 64; kk++) {
            float pv[4], vv[4];
            #pragma unroll
            for (int u = 0; u < 4; u++) pv[u] = SC[(ty * 4 + u) * 64 + kk];
            #pragma unroll
            for (int v = 0; v < 4; v++) vv[v] = KV[kk * 64 + tx * 4 + v];
            #pragma unroll
            for (int u = 0; u < 4; u++)
                #pragma unroll
                for (int v = 0; v < 4; v++) acc[u][v] += pv[u] * vv[v];
        }
    }
    __syncthreads();
    if (tid < 64) SC[tid] = Lacc;
    __syncthreads();
    #pragma unroll
    for (int u = 0; u < 4; u++) {
        int r = ty * 4 + u;
        float invl = 1.f / (SC[r] + 1e-6f);
        #pragma unroll
        for (int v = 0; v < 4; v++)
            g_att[(size_t)(ib * 64 + r) * DM + h * 64 + tx * 4 + v] = acc[u][v] * invl;
    }
}

// ---------------- layernorm ----------------
__global__ void layernorm_k(const float* __restrict__ X, const float* __restrict__ g,
                            const float* __restrict__ b, float* __restrict__ Y) {
    int t = blockIdx.x;
    __shared__ float sm[8];
    const float* x = X + (size_t)t * DM;
    float loc[8];
    float s = 0.f, ss = 0.f;
    #pragma unroll
    for (int i = 0; i < 8; i++) {
        float v = x[threadIdx.x + i * 256];
        loc[i] = v; s += v; ss += v * v;
    }
    s  = block_sum_256(s, sm);
    ss = block_sum_256(ss, sm);
    float mu  = s * (1.f / DM);
    float var = ss * (1.f / DM) - mu * mu;
    float inv = rsqrtf(var + 1e-5f);
    float* y = Y + (size_t)t * DM;
    #pragma unroll
    for (int i = 0; i < 8; i++) {
        int d = threadIdx.x + i * 256;
        y[d] = (loc[i] - mu) * inv * g[d] + b[d];
    }
}

// ---------------- moe bookkeeping ----------------
__global__ void init_moe_k() {
    if (threadIdx.x < NE) g_cnt[threadIdx.x] = 0;
    if (threadIdx.x == NE) g_aux = 0.f;
}

__global__ void gate_k(const float* __restrict__ X2, const float* __restrict__ GW) {
    int t = blockIdx.x;                 // 128 threads
    __shared__ float sm[4][4];
    float p0 = 0.f, p1 = 0.f, p2 = 0.f, p3 = 0.f;
    for (int d = threadIdx.x; d < DM; d += 128) {
        float xv = X2[(size_t)t * DM + d];
        p0 += xv * GW[0 * DM + d];
        p1 += xv * GW[1 * DM + d];
        p2 += xv * GW[2 * DM + d];
        p3 += xv * GW[3 * DM + d];
    }
    #pragma unroll
    for (int o = 16; o > 0; o >>= 1) {
        p0 += __shfl_down_sync(0xffffffffu, p0, o);
        p1 += __shfl_down_sync(0xffffffffu, p1, o);
        p2 += __shfl_down_sync(0xffffffffu, p2, o);
        p3 += __shfl_down_sync(0xffffffffu, p3, o);
    }
    int w = threadIdx.x >> 5;
    if ((threadIdx.x & 31) == 0) {
        sm[w][0] = p0; sm[w][1] = p1; sm[w][2] = p2; sm[w][3] = p3;
    }
    __syncthreads();
    if (threadIdx.x == 0) {
        float l[4];
        #pragma unroll
        for (int e = 0; e < 4; e++) l[e] = sm[0][e] + sm[1][e] + sm[2][e] + sm[3][e];
        float mean = (l[0] + l[1] + l[2] + l[3]) * 0.25f;
        float var = 0.f;
        #pragma unroll
        for (int e = 0; e < 4; e++) var += (l[e] - mean) * (l[e] - mean);
        var *= (1.f / 3.f);                           // ddof=1
        atomicAdd(&g_aux, var * (1.f / SQ));
        float m = fmaxf(fmaxf(l[0], l[1]), fmaxf(l[2], l[3]));
        float pe[4]; float Z = 0.f;
        #pragma unroll
        for (int e = 0; e < 4; e++) { pe[e] = expf(l[e] - m); Z += pe[e]; }
        #pragma unroll
        for (int e = 0; e < 4; e++) pe[e] /= Z;
        int i1 = 0;
        for (int e = 1; e < 4; e++) if (pe[e] > pe[i1]) i1 = e;
        int i2 = -1;
        for (int e = 0; e < 4; e++) if (e != i1 && (i2 < 0 || pe[e] > pe[i2])) i2 = e;
        float den = pe[i1] + pe[i2];
        int s0 = atomicAdd(&g_cnt[i1], 1);
        g_etok[i1 * SQ + s0] = t;
        g_tok_slot[2 * t] = i1 * SQ + s0;
        g_tok_w[2 * t] = pe[i1] / den;
        int s1 = atomicAdd(&g_cnt[i2], 1);
        g_etok[i2 * SQ + s1] = t;
        g_tok_slot[2 * t + 1] = i2 * SQ + s1;
        g_tok_w[2 * t + 1] = pe[i2] / den;
    }
}

__global__ void silu_mul_k() {
    int row = blockIdx.x;               // NE*SQ rows
    int e = row >> 10;
    int slot = row & 1023;
    if (slot >= g_cnt[e]) return;
    size_t base = (size_t)row * DF;
    for (int f = threadIdx.x; f < DF; f += blockDim.x) {
        float h1 = g_h1[base + f], h3 = g_h3[base + f];
        g_h1[base + f] = h1 / (1.f + __expf(-h1)) * h3;
    }
}

// ---------------- combine moe + residual + ln2 + fin-ln ----------------
__global__ void combine_ln_k(const float* __restrict__ Y, const float* __restrict__ X2,
                             const float* __restrict__ ln2g, const float* __restrict__ ln2b,
                             const float* __restrict__ fing, const float* __restrict__ finb,
                             float* __restrict__ Out) {
    int t = blockIdx.x;
    __shared__ float sm[8];
    int f0 = g_tok_slot[t * 2], f1 = g_tok_slot[t * 2 + 1];
    float w0 = g_tok_w[t * 2], w1 = g_tok_w[t * 2 + 1];
    const float* y0 = Y + (size_t)f0 * DM;
    const float* y1 = Y + (size_t)f1 * DM;
    float loc[8];
    float s = 0.f, ss = 0.f;
    #pragma unroll
    for (int i = 0; i < 8; i++) {
        int d = threadIdx.x + i * 256;
        float a = w0 * y0[d] + w1 * y1[d] + X2[(size_t)t * DM + d];
        loc[i] = a; s += a; ss += a * a;
    }
    s  = block_sum_256(s, sm);
    ss = block_sum_256(ss, sm);
    float mu  = s * (1.f / DM);
    float var = ss * (1.f / DM) - mu * mu;
    float inv = rsqrtf(var + 1e-5f);
    float s2 = 0.f, ss2 = 0.f;
    #pragma unroll
    for (int i = 0; i < 8; i++) {
        int d = threadIdx.x + i * 256;
        float bn = (loc[i] - mu) * inv * ln2g[d] + ln2b[d];
        loc[i] = bn; s2 += bn; ss2 += bn * bn;
    }
    s2  = block_sum_256(s2, sm);
    ss2 = block_sum_256(ss2, sm);
    float mu2  = s2 * (1.f / DM);
    float var2 = ss2 * (1.f / DM) - mu2 * mu2;
    float inv2 = rsqrtf(var2 + 1e-5f);
    #pragma unroll
    for (int i = 0; i < 8; i++) {
        int d = threadIdx.x + i * 256;
        Out[(size_t)t * DM + d] = (loc[i] - mu2) * inv2 * fing[d] + finb[d];
    }
}

__global__ void aux_write_k(float* out, int out_size) {
    if (out_size > SQ * VOC) out[(size_t)SQ * VOC] = g_aux;
}

// ---------------- launch ----------------
extern "C" void kernel_launch(void* const* d_in, const int* in_sizes, int n_in,
                              void* d_out, int out_size) {
    const int*   tokens = (const int*)d_in[0];
    const float* emb    = (const float*)d_in[1];
    const float* wq     = (const float*)d_in[2];
    const float* wk     = (const float*)d_in[3];
    const float* wv     = (const float*)d_in[4];
    const float* wo     = (const float*)d_in[5];
    const float* ln1_g  = (const float*)d_in[6];
    const float* ln1_b  = (const float*)d_in[7];
    const float* gate_w = (const float*)d_in[8];
    const float* w1     = (const float*)d_in[9];
    const float* w2     = (const float*)d_in[10];
    const float* w3     = (const float*)d_in[11];
    const float* ln2_g  = (const float*)d_in[12];
    const float* ln2_b  = (const float*)d_in[13];
    const float* fin_g  = (const float*)d_in[14];
    const float* fin_b  = (const float*)d_in[15];
    const float* head_w = (const float*)d_in[16];
    float* out = (float*)d_out;

    float *p_x, *p_q, *p_k, *p_v, *p_att, *p_x1, *p_x2, *p_x3, *p_h1, *p_h3, *p_y;
    cudaGetSymbolAddress((void**)&p_x,  g_x);
    cudaGetSymbolAddress((void**)&p_q,  g_q);
    cudaGetSymbolAddress((void**)&p_k,  g_k);
    cudaGetSymbolAddress((void**)&p_v,  g_v);
    cudaGetSymbolAddress((void**)&p_att, g_att);
    cudaGetSymbolAddress((void**)&p_x1, g_x1);
    cudaGetSymbolAddress((void**)&p_x2, g_x2);
    cudaGetSymbolAddress((void**)&p_x3, g_x3);
    cudaGetSymbolAddress((void**)&p_h1, g_h1);
    cudaGetSymbolAddress((void**)&p_h3, g_h3);
    cudaGetSymbolAddress((void**)&p_y,  g_y);

    ropetab_k<<<SQ, 32>>>();
    embed_k<<<SQ, 256>>>(tokens, emb);

    gemm_plain<<<dim3(DM / 128, SQ / 128), 256>>>(p_x, wq, p_q, SQ, DM, DM, nullptr);
    gemm_plain<<<dim3(DM / 128, SQ / 128), 256>>>(p_x, wk, p_k, SQ, DM, DM, nullptr);
    gemm_plain<<<dim3(DM / 128, SQ / 128), 256>>>(p_x, wv, p_v, SQ, DM, DM, nullptr);

    rope_k<<<SQ, 1024>>>();
    attn_k<<<dim3(NH, NBLK), 256>>>();

    gemm_plain<<<dim3(DM / 128, SQ / 128), 256>>>(p_att, wo, p_x1, SQ, DM, DM, p_x);
    layernorm_k<<<SQ, 256>>>(p_x1, ln1_g, ln1_b, p_x2);

    init_moe_k<<<1, 32>>>();
    gate_k<<<SQ, 128>>>(p_x2, gate_w);

    moe_gemm_in<<<dim3(DF / 128, SQ / 128, NE), 256>>>(p_x2, w1, p_h1);
    moe_gemm_in<<<dim3(DF / 128, SQ / 128, NE), 256>>>(p_x2, w3, p_h3);
    silu_mul_k<<<NE * SQ, 256>>>();
    moe_gemm_out<<<dim3(DM / 128, SQ / 128, NE), 256>>>(p_h1, w2, p_y);

    combine_ln_k<<<SQ, 256>>>(p_y, p_x2, ln2_g, ln2_b, fin_g, fin_b, p_x3);

    gemm_plain<<<dim3((VOC + 127) / 128, SQ / 128), 256>>>(p_x3, head_w, out, SQ, VOC, DM, nullptr);
    aux_write_k<<<1, 1>>>(out, out_size);
}

// round 8
// speedup vs baseline: 2.7822x; 2.7748x over previous
#include <cuda_runtime.h>
#include <cuda_bf16.h>
#include <math.h>
#include <stdint.h>

#define SQ   1024
#define DM   2048
#define NH   32
#define NBLK 16
#define NE   4
#define DF   8192
#define VOC  50257
#define QKVN 6144

// ---------------- scratch ----------------
__device__ float g_x  [SQ*DM];
__device__ float g_qkv[SQ*QKVN];
__device__ float g_x1 [SQ*DM];
__device__ float g_x2 [SQ*DM];
__device__ float g_cos[SQ*32];
__device__ float g_sin[SQ*32];
__device__ int   g_cnt[NE];
__device__ int   g_etok[NE*SQ];
__device__ int   g_tok_slot[SQ*2];
__device__ float g_tok_w  [SQ*2];
__device__ float g_h1[NE*SQ*DF];
__device__ float g_h3[NE*SQ*DF];
__device__ float g_y [NE*SQ*DM];
__device__ float g_aux;

__device__ __align__(16) __nv_bfloat16 g_xh [SQ*DM],  g_xl [SQ*DM];
__device__ __align__(16) __nv_bfloat16 g_ath[SQ*DM],  g_atl[SQ*DM];
__device__ __align__(16) __nv_bfloat16 g_x2h[SQ*DM],  g_x2l[SQ*DM];
__device__ __align__(16) __nv_bfloat16 g_x3h[SQ*DM],  g_x3l[SQ*DM];
__device__ __align__(16) __nv_bfloat16 g_hh [NE*SQ*DF], g_hl[NE*SQ*DF];
__device__ __align__(16) __nv_bfloat16 g_wqkvh[3*DM*DM], g_wqkvl[3*DM*DM];
__device__ __align__(16) __nv_bfloat16 g_woh [DM*DM],    g_wol [DM*DM];
__device__ __align__(16) __nv_bfloat16 g_w1h [NE*DF*DM], g_w1l [NE*DF*DM];
__device__ __align__(16) __nv_bfloat16 g_w3h [NE*DF*DM], g_w3l [NE*DF*DM];
__device__ __align__(16) __nv_bfloat16 g_w2h [NE*DM*DF], g_w2l [NE*DM*DF];
__device__ __align__(16) __nv_bfloat16 g_hwh [VOC*DM],   g_hwl [VOC*DM];

// ---------------- helpers ----------------
__device__ __forceinline__ uint32_t s2u(const void* p) {
    uint32_t a;
    asm("{ .reg .u64 t; cvta.to.shared.u64 t, %1; cvt.u32.u64 %0, t; }" : "=r"(a) : "l"(p));
    return a;
}
__device__ __forceinline__ void cpa16(uint32_t dst, const void* src, int sz) {
    asm volatile("cp.async.cg.shared.global [%0], [%1], 16, %2;" :: "r"(dst), "l"(src), "r"(sz) : "memory");
}
#define CPA_COMMIT() asm volatile("cp.async.commit_group;" ::: "memory")

__device__ __forceinline__ void ldsm4(uint32_t* r, uint32_t addr) {
    asm volatile("ldmatrix.sync.aligned.m8n8.x4.shared.b16 {%0,%1,%2,%3}, [%4];"
        : "=r"(r[0]), "=r"(r[1]), "=r"(r[2]), "=r"(r[3]) : "r"(addr));
}
__device__ __forceinline__ void mma16816(float* d, const uint32_t* a, const uint32_t* b) {
    asm volatile("mma.sync.aligned.m16n8k16.row.col.f32.bf16.bf16.f32 "
        "{%0,%1,%2,%3}, {%4,%5,%6,%7}, {%8,%9}, {%0,%1,%2,%3};"
        : "+f"(d[0]), "+f"(d[1]), "+f"(d[2]), "+f"(d[3])
        : "r"(a[0]), "r"(a[1]), "r"(a[2]), "r"(a[3]), "r"(b[0]), "r"(b[1]));
}
__device__ __forceinline__ void split2(float v, __nv_bfloat16* h, __nv_bfloat16* l) {
    __nv_bfloat16 hh = __float2bfloat16(v);
    *h = hh;
    *l = __float2bfloat16(v - __bfloat162float(hh));
}
__device__ __forceinline__ float block_sum_256(float v, float* sm) {
    __syncthreads();
    #pragma unroll
    for (int o = 16; o > 0; o >>= 1) v += __shfl_down_sync(0xffffffffu, v, o);
    if ((threadIdx.x & 31) == 0) sm[threadIdx.x >> 5] = v;
    __syncthreads();
    float r = 0.f;
    if (threadIdx.x < 8) {
        r = sm[threadIdx.x];
        #pragma unroll
        for (int o = 4; o > 0; o >>= 1) r += __shfl_down_sync(0x000000ffu, r, o);
        if (threadIdx.x == 0) sm[0] = r;
    }
    __syncthreads();
    return sm[0];
}

// ---------------- mma.sync bf16x3 GEMM: C[m][n] = sum_k A[m][k]*B[n][k] ----------------
// CTA tile 128x128, K-chunk 64, double-buffered cp.async, 8 warps (4M x 2N), warp 32x64.
#define GSMEM_BYTES (2*65536 + 1024)

#define ISSUE_CHUNK(KT, BUF) do {                                              \
    uint32_t bb_ = base + (uint32_t)(BUF) * 65536u;                            \
    long k0_ = (long)(KT) * 64;                                                \
    _Pragma("unroll")                                                          \
    for (int u = tid; u < 1024; u += 256) {                                    \
        int r_ = u >> 3, kc_ = u & 7;                                          \
        uint32_t smo_ = (uint32_t)(r_ * 128 + ((kc_ ^ (r_ & 7)) << 4));        \
        int rv_ = rowsm[r_];                                                   \
        int okA_ = (rv_ >= 0) ? 16 : 0;                                        \
        long ga_ = ((rv_ >= 0) ? (long)rv_ : 0) * (long)K + k0_ + kc_ * 8;     \
        cpa16(bb_ + smo_,          Ah + ga_, okA_);                            \
        cpa16(bb_ + 16384 + smo_,  Al + ga_, okA_);                            \
        int nn_ = n0 + r_;                                                     \
        int okB_ = (nn_ < N) ? 16 : 0;                                         \
        long gb_ = ((nn_ < N) ? (long)nn_ : 0) * (long)K + k0_ + kc_ * 8;      \
        cpa16(bb_ + 32768 + smo_,  Bh + gb_, okB_);                            \
        cpa16(bb_ + 49152 + smo_,  Bl + gb_, okB_);                            \
    }                                                                          \
    CPA_COMMIT();                                                              \
} while (0)

__global__ __launch_bounds__(256, 1)
void mma_gemm(const __nv_bfloat16* __restrict__ Ah, const __nv_bfloat16* __restrict__ Al,
              const __nv_bfloat16* __restrict__ Bh, const __nv_bfloat16* __restrict__ Bl,
              float* __restrict__ C, const float* __restrict__ Res,
              const int* __restrict__ gatherB,
              int M, int N, int K, int ldc,
              long aStrE, long bStrE, long cStrE)
{
    extern __shared__ char dsm[];
    __shared__ int rowsm[128];

    int e = blockIdx.z;
    if (M < 0) M = g_cnt[e];
    int m0 = blockIdx.x * 128;
    if (m0 >= M) return;
    int n0 = blockIdx.y * 128;
    Ah += (long)e * aStrE; Al += (long)e * aStrE;
    Bh += (long)e * bStrE; Bl += (long)e * bStrE;
    C  += (long)e * cStrE;
    const int* gth = gatherB ? (gatherB + e * SQ) : nullptr;

    int tid = threadIdx.x, wid = tid >> 5, lane = tid & 31;
    if (tid < 128) {
        int m = m0 + tid;
        rowsm[tid] = (m < M) ? (gth ? gth[m] : m) : -1;
    }
    __syncthreads();

    uint32_t base = (s2u(dsm) + 1023u) & ~1023u;
    int m0w = (wid >> 1) * 32;
    int n0w = (wid & 1) * 64;
    int tq = lane >> 3, li = lane & 7;

    // precomputed ldmatrix lane rows
    int rA0 = m0w + (tq & 1) * 8 + li;          // mt adds +16
    int rB0 = n0w + (tq >> 1) * 8 + li;         // g adds +16 per group
    int kuA = tq >> 1;                          // + ks*2
    int kuB = tq & 1;                           // + ks*2

    float acc[2][8][4];
    #pragma unroll
    for (int mt = 0; mt < 2; mt++)
        #pragma unroll
        for (int nt = 0; nt < 8; nt++)
            #pragma unroll
            for (int c = 0; c < 4; c++) acc[mt][nt][c] = 0.f;

    int nk = K >> 6;
    ISSUE_CHUNK(0, 0);

    for (int kt = 0; kt < nk; kt++) {
        int buf = kt & 1;
        if (kt + 1 < nk) {
            ISSUE_CHUNK(kt + 1, (kt + 1) & 1);
            asm volatile("cp.async.wait_group 1;" ::: "memory");
        } else {
            asm volatile("cp.async.wait_group 0;" ::: "memory");
        }
        __syncthreads();

        uint32_t bb = base + (uint32_t)buf * 65536u;
        #pragma unroll
        for (int ks = 0; ks < 4; ks++) {
            uint32_t ahf[2][4], alf[2][4];
            #pragma unroll
            for (int mt = 0; mt < 2; mt++) {
                int row = rA0 + mt * 16;
                uint32_t ad = bb + (uint32_t)(row * 128 + (((kuA + ks * 2) ^ (row & 7)) << 4));
                ldsm4(ahf[mt], ad);
                ldsm4(alf[mt], ad + 16384);
            }
            uint32_t bhf[4][4], blf[4][4];
            #pragma unroll
            for (int g = 0; g < 4; g++) {
                int row = rB0 + g * 16;
                uint32_t bd = bb + 32768 + (uint32_t)(row * 128 + (((kuB + ks * 2) ^ (row & 7)) << 4));
                ldsm4(bhf[g], bd);
                ldsm4(blf[g], bd + 16384);
            }
            #pragma unroll
            for (int mt = 0; mt < 2; mt++)
                #pragma unroll
                for (int g = 0; g < 4; g++)
                    #pragma unroll
                    for (int hh = 0; hh < 2; hh++) {
                        float* d = acc[mt][g * 2 + hh];
                        mma16816(d, ahf[mt], &bhf[g][hh * 2]);
                        mma16816(d, ahf[mt], &blf[g][hh * 2]);
                        mma16816(d, alf[mt], &bhf[g][hh * 2]);
                    }
        }
        __syncthreads();
    }

    // epilogue
    #pragma unroll
    for (int mt = 0; mt < 2; mt++) {
        int row = m0 + m0w + mt * 16 + (lane >> 2);
        #pragma unroll
        for (int nt = 0; nt < 8; nt++) {
            int col = n0 + n0w + nt * 8 + (lane & 3) * 2;
            float* d = acc[mt][nt];
            if (row < M) {
                long o = (long)row * ldc;
                if (col < N)     C[o + col]     = d[0] + (Res ? Res[o + col] : 0.f);
                if (col + 1 < N) C[o + col + 1] = d[1] + (Res ? Res[o + col + 1] : 0.f);
            }
            if (row + 8 < M) {
                long o = (long)(row + 8) * ldc;
                if (col < N)     C[o + col]     = d[2] + (Res ? Res[o + col] : 0.f);
                if (col + 1 < N) C[o + col + 1] = d[3] + (Res ? Res[o + col + 1] : 0.f);
            }
        }
    }
}

// ---------------- fp32 -> bf16 hi/lo split ----------------
__global__ void cvt_split_k(const float4* __restrict__ src, __nv_bfloat16* __restrict__ hi,
                            __nv_bfloat16* __restrict__ lo, long n4) {
    long i = (long)blockIdx.x * blockDim.x + threadIdx.x;
    long stride = (long)gridDim.x * blockDim.x;
    for (; i < n4; i += stride) {
        float4 v = src[i];
        __align__(8) __nv_bfloat16 h[4], l[4];
        split2(v.x, &h[0], &l[0]); split2(v.y, &h[1], &l[1]);
        split2(v.z, &h[2], &l[2]); split2(v.w, &h[3], &l[3]);
        *reinterpret_cast<uint2*>(hi + 4 * i) = *reinterpret_cast<uint2*>(h);
        *reinterpret_cast<uint2*>(lo + 4 * i) = *reinterpret_cast<uint2*>(l);
    }
}

__global__ void ropetab_k() {
    int s = blockIdx.x, i = threadIdx.x;
    double inv = exp(-((double)(2 * i) / 64.0) * log(10000.0));
    double ang = (double)s * inv;
    g_cos[s * 32 + i] = (float)cos(ang);
    g_sin[s * 32 + i] = (float)sin(ang);
}

__global__ void embed_k(const int* __restrict__ tok, const float* __restrict__ emb) {
    int t = blockIdx.x;
    int row = tok[t];
    const float4* src = (const float4*)(emb + (size_t)row * DM);
    for (int i = threadIdx.x; i < DM / 4; i += blockDim.x) {
        float4 v = src[i];
        *(float4*)(g_x + (size_t)t * DM + 4 * i) = v;
        __align__(8) __nv_bfloat16 h[4], l[4];
        split2(v.x, &h[0], &l[0]); split2(v.y, &h[1], &l[1]);
        split2(v.z, &h[2], &l[2]); split2(v.w, &h[3], &l[3]);
        *reinterpret_cast<uint2*>(g_xh + (size_t)t * DM + 4 * i) = *reinterpret_cast<uint2*>(h);
        *reinterpret_cast<uint2*>(g_xl + (size_t)t * DM + 4 * i) = *reinterpret_cast<uint2*>(l);
    }
}

__global__ void rope_k() {
    int s = blockIdx.x;
    int idx = threadIdx.x;
    int h = idx >> 5, i = idx & 31;
    float c = g_cos[s * 32 + i], sn = g_sin[s * 32 + i];
    size_t base = (size_t)s * QKVN + h * 64 + 2 * i;
    float q0 = g_qkv[base], q1 = g_qkv[base + 1];
    g_qkv[base]     = q0 * c - q1 * sn;
    g_qkv[base + 1] = q0 * sn + q1 * c;
    float k0 = g_qkv[base + 2048], k1 = g_qkv[base + 2049];
    g_qkv[base + 2048] = k0 * c - k1 * sn;
    g_qkv[base + 2049] = k0 * sn + k1 * c;
}

// ---------------- attention (reference per-block max semantics) ----------------
__global__ void attn_k() {
    int h  = blockIdx.x;
    int ib = blockIdx.y;
    __shared__ float Qs[64 * 64];
    __shared__ float KV[64 * 64];
    __shared__ float SC[64 * 64];
    int tid = threadIdx.x;
    int tx = tid & 15, ty = tid >> 4;

    for (int idx = tid; idx < 1024; idx += 256) {
        int r = idx >> 4, c4 = (idx & 15) * 4;
        *(float4*)&Qs[r * 64 + c4] =
            *(const float4*)&g_qkv[(size_t)(ib * 64 + r) * QKVN + h * 64 + c4];
    }
    float acc[4][4];
    #pragma unroll
    for (int u = 0; u < 4; u++)
        #pragma unroll
        for (int v = 0; v < 4; v++) acc[u][v] = 0.f;
    float Lacc = 0.f;

    for (int j = 0; j <= ib; j++) {
        __syncthreads();
        for (int idx = tid; idx < 1024; idx += 256) {
            int r = idx >> 4, c4 = (idx & 15) * 4;
            float4 kv = *(const float4*)&g_qkv[(size_t)(j * 64 + r) * QKVN + 2048 + h * 64 + c4];
            KV[(c4 + 0) * 64 + r] = kv.x; KV[(c4 + 1) * 64 + r] = kv.y;
            KV[(c4 + 2) * 64 + r] = kv.z; KV[(c4 + 3) * 64 + r] = kv.w;
        }
        __syncthreads();
        {
            float sc[4][4];
            #pragma unroll
            for (int u = 0; u < 4; u++)
                #pragma unroll
                for (int v = 0; v < 4; v++) sc[u][v] = 0.f;
            for (int kk = 0; kk < 64; kk++) {
                float qv[4], kvv[4];
                #pragma unroll
                for (int u = 0; u < 4; u++) qv[u] = Qs[(ty * 4 + u) * 64 + kk];
                #pragma unroll
                for (int v = 0; v < 4; v++) kvv[v] = KV[kk * 64 + tx * 4 + v];
                #pragma unroll
                for (int u = 0; u < 4; u++)
                    #pragma unroll
                    for (int v = 0; v < 4; v++) sc[u][v] += qv[u] * kvv[v];
            }
            #pragma unroll
            for (int u = 0; u < 4; u++)
                #pragma unroll
                for (int v = 0; v < 4; v++)
                    SC[(ty * 4 + u) * 64 + tx * 4 + v] = sc[u][v] * 0.125f;
        }
        __syncthreads();
        if (tid < 64) {
            int r = tid;
            int kmax = (j == ib) ? r : 63;
            float m = -1e30f;
            for (int kk = 0; kk <= kmax; kk++) m = fmaxf(m, SC[r * 64 + kk]);
            float ssum = 0.f;
            for (int kk = 0; kk < 64; kk++) {
                float p = (kk <= kmax) ? __expf(SC[r * 64 + kk] - m) : 0.f;
                SC[r * 64 + kk] = p;
                ssum += p;
            }
            Lacc += ssum;
        }
        __syncthreads();
        for (int idx = tid; idx < 1024; idx += 256) {
            int r = idx >> 4, c4 = (idx & 15) * 4;
            *(float4*)&KV[r * 64 + c4] =
                *(const float4*)&g_qkv[(size_t)(j * 64 + r) * QKVN + 4096 + h * 64 + c4];
        }
        __syncthreads();
        for (int kk = 0; kk < 64; kk++) {
            float pv[4], vv[4];
            #pragma unroll
            for (int u = 0; u < 4; u++) pv[u] = SC[(ty * 4 + u) * 64 + kk];
            #pragma unroll
            for (int v = 0; v < 4; v++) vv[v] = KV[kk * 64 + tx * 4 + v];
            #pragma unroll
            for (int u = 0; u < 4; u++)
                #pragma unroll
                for (int v = 0; v < 4; v++) acc[u][v] += pv[u] * vv[v];
        }
    }
    __syncthreads();
    if (tid < 64) SC[tid] = Lacc;
    __syncthreads();
    #pragma unroll
    for (int u = 0; u < 4; u++) {
        int r = ty * 4 + u;
        float invl = 1.f / (SC[r] + 1e-6f);
        #pragma unroll
        for (int v = 0; v < 4; v++) {
            float val = acc[u][v] * invl;
            size_t o = (size_t)(ib * 64 + r) * DM + h * 64 + tx * 4 + v;
            __nv_bfloat16 hh, ll;
            split2(val, &hh, &ll);
            g_ath[o] = hh; g_atl[o] = ll;
        }
    }
}

// ---------------- layernorm (+ split) ----------------
__global__ void layernorm_k(const float* __restrict__ X, const float* __restrict__ g,
                            const float* __restrict__ b, float* __restrict__ Y,
                            __nv_bfloat16* __restrict__ Yh, __nv_bfloat16* __restrict__ Yl) {
    int t = blockIdx.x;
    __shared__ float sm[8];
    const float* x = X + (size_t)t * DM;
    float loc[8];
    float s = 0.f, ss = 0.f;
    #pragma unroll
    for (int i = 0; i < 8; i++) {
        float v = x[threadIdx.x + i * 256];
        loc[i] = v; s += v; ss += v * v;
    }
    s  = block_sum_256(s, sm);
    ss = block_sum_256(ss, sm);
    float mu  = s * (1.f / DM);
    float var = ss * (1.f / DM) - mu * mu;
    float inv = rsqrtf(var + 1e-5f);
    #pragma unroll
    for (int i = 0; i < 8; i++) {
        int d = threadIdx.x + i * 256;
        float v = (loc[i] - mu) * inv * g[d] + b[d];
        Y[(size_t)t * DM + d] = v;
        __nv_bfloat16 hh, ll;
        split2(v, &hh, &ll);
        Yh[(size_t)t * DM + d] = hh;
        Yl[(size_t)t * DM + d] = ll;
    }
}

__global__ void init_moe_k() {
    if (threadIdx.x < NE) g_cnt[threadIdx.x] = 0;
    if (threadIdx.x == NE) g_aux = 0.f;
}

__global__ void gate_k(const float* __restrict__ X2, const float* __restrict__ GW) {
    int t = blockIdx.x;
    __shared__ float sm[4][4];
    float p0 = 0.f, p1 = 0.f, p2 = 0.f, p3 = 0.f;
    for (int d = threadIdx.x; d < DM; d += 128) {
        float xv = X2[(size_t)t * DM + d];
        p0 += xv * GW[0 * DM + d]; p1 += xv * GW[1 * DM + d];
        p2 += xv * GW[2 * DM + d]; p3 += xv * GW[3 * DM + d];
    }
    #pragma unroll
    for (int o = 16; o > 0; o >>= 1) {
        p0 += __shfl_down_sync(0xffffffffu, p0, o);
        p1 += __shfl_down_sync(0xffffffffu, p1, o);
        p2 += __shfl_down_sync(0xffffffffu, p2, o);
        p3 += __shfl_down_sync(0xffffffffu, p3, o);
    }
    int w = threadIdx.x >> 5;
    if ((threadIdx.x & 31) == 0) { sm[w][0] = p0; sm[w][1] = p1; sm[w][2] = p2; sm[w][3] = p3; }
    __syncthreads();
    if (threadIdx.x == 0) {
        float l[4];
        #pragma unroll
        for (int e = 0; e < 4; e++) l[e] = sm[0][e] + sm[1][e] + sm[2][e] + sm[3][e];
        float mean = (l[0] + l[1] + l[2] + l[3]) * 0.25f;
        float var = 0.f;
        #pragma unroll
        for (int e = 0; e < 4; e++) var += (l[e] - mean) * (l[e] - mean);
        var *= (1.f / 3.f);
        atomicAdd(&g_aux, var * (1.f / SQ));
        float m = fmaxf(fmaxf(l[0], l[1]), fmaxf(l[2], l[3]));
        float pe[4]; float Z = 0.f;
        #pragma unroll
        for (int e = 0; e < 4; e++) { pe[e] = expf(l[e] - m); Z += pe[e]; }
        #pragma unroll
        for (int e = 0; e < 4; e++) pe[e] /= Z;
        int i1 = 0;
        for (int e = 1; e < 4; e++) if (pe[e] > pe[i1]) i1 = e;
        int i2 = -1;
        for (int e = 0; e < 4; e++) if (e != i1 && (i2 < 0 || pe[e] > pe[i2])) i2 = e;
        float den = pe[i1] + pe[i2];
        int s0 = atomicAdd(&g_cnt[i1], 1);
        g_etok[i1 * SQ + s0] = t;
        g_tok_slot[2 * t] = i1 * SQ + s0;
        g_tok_w[2 * t] = pe[i1] / den;
        int s1 = atomicAdd(&g_cnt[i2], 1);
        g_etok[i2 * SQ + s1] = t;
        g_tok_slot[2 * t + 1] = i2 * SQ + s1;
        g_tok_w[2 * t + 1] = pe[i2] / den;
    }
}

__global__ void silu_split_k() {
    int row = blockIdx.x;
    int e = row >> 10;
    int slot = row & 1023;
    if (slot >= g_cnt[e]) return;
    size_t base = (size_t)row * DF;
    for (int f = threadIdx.x; f < DF; f += blockDim.x) {
        float h1 = g_h1[base + f], h3 = g_h3[base + f];
        float v = h1 / (1.f + __expf(-h1)) * h3;
        __nv_bfloat16 hh, ll;
        split2(v, &hh, &ll);
        g_hh[base + f] = hh;
        g_hl[base + f] = ll;
    }
}

__global__ void combine_ln_k(const float* __restrict__ Y, const float* __restrict__ X2,
                             const float* __restrict__ ln2g, const float* __restrict__ ln2b,
                             const float* __restrict__ fing, const float* __restrict__ finb) {
    int t = blockIdx.x;
    __shared__ float sm[8];
    int f0 = g_tok_slot[t * 2], f1 = g_tok_slot[t * 2 + 1];
    float w0 = g_tok_w[t * 2], w1 = g_tok_w[t * 2 + 1];
    const float* y0 = Y + (size_t)f0 * DM;
    const float* y1 = Y + (size_t)f1 * DM;
    float loc[8];
    float s = 0.f, ss = 0.f;
    #pragma unroll
    for (int i = 0; i < 8; i++) {
        int d = threadIdx.x + i * 256;
        float a = w0 * y0[d] + w1 * y1[d] + X2[(size_t)t * DM + d];
        loc[i] = a; s += a; ss += a * a;
    }
    s  = block_sum_256(s, sm);
    ss = block_sum_256(ss, sm);
    float mu  = s * (1.f / DM);
    float var = ss * (1.f / DM) - mu * mu;
    float inv = rsqrtf(var + 1e-5f);
    float s2 = 0.f, ss2 = 0.f;
    #pragma unroll
    for (int i = 0; i < 8; i++) {
        int d = threadIdx.x + i * 256;
        float bn = (loc[i] - mu) * inv * ln2g[d] + ln2b[d];
        loc[i] = bn; s2 += bn; ss2 += bn * bn;
    }
    s2  = block_sum_256(s2, sm);
    ss2 = block_sum_256(ss2, sm);
    float mu2  = s2 * (1.f / DM);
    float var2 = ss2 * (1.f / DM) - mu2 * mu2;
    float inv2 = rsqrtf(var2 + 1e-5f);
    #pragma unroll
    for (int i = 0; i < 8; i++) {
        int d = threadIdx.x + i * 256;
        float v = (loc[i] - mu2) * inv2 * fing[d] + finb[d];
        __nv_bfloat16 hh, ll;
        split2(v, &hh, &ll);
        g_x3h[(size_t)t * DM + d] = hh;
        g_x3l[(size_t)t * DM + d] = ll;
    }
}

__global__ void aux_write_k(float* out, int out_size) {
    if (out_size > SQ * VOC) out[(size_t)SQ * VOC] = g_aux;
}

// ---------------- launch ----------------
extern "C" void kernel_launch(void* const* d_in, const int* in_sizes, int n_in,
                              void* d_out, int out_size) {
    const int*   tokens = (const int*)d_in[0];
    const float* emb    = (const float*)d_in[1];
    const float* wq     = (const float*)d_in[2];
    const float* wk     = (const float*)d_in[3];
    const float* wv     = (const float*)d_in[4];
    const float* wo     = (const float*)d_in[5];
    const float* ln1_g  = (const float*)d_in[6];
    const float* ln1_b  = (const float*)d_in[7];
    const float* gate_w = (const float*)d_in[8];
    const float* w1     = (const float*)d_in[9];
    const float* w2     = (const float*)d_in[10];
    const float* w3     = (const float*)d_in[11];
    const float* ln2_g  = (const float*)d_in[12];
    const float* ln2_b  = (const float*)d_in[13];
    const float* fin_g  = (const float*)d_in[14];
    const float* fin_b  = (const float*)d_in[15];
    const float* head_w = (const float*)d_in[16];
    float* out = (float*)d_out;

    cudaFuncSetAttribute(mma_gemm, cudaFuncAttributeMaxDynamicSharedMemorySize, GSMEM_BYTES);

    float *p_x, *p_qkv, *p_x1, *p_x2, *p_h1, *p_h3, *p_y;
    __nv_bfloat16 *p_xh, *p_xl, *p_ath, *p_atl, *p_x2h, *p_x2l, *p_x3h, *p_x3l, *p_hh, *p_hl;
    __nv_bfloat16 *p_wqkvh, *p_wqkvl, *p_woh, *p_wol, *p_w1h, *p_w1l, *p_w3h, *p_w3l, *p_w2h, *p_w2l, *p_hwh, *p_hwl;
    int *p_etok;
    cudaGetSymbolAddress((void**)&p_x, g_x);     cudaGetSymbolAddress((void**)&p_qkv, g_qkv);
    cudaGetSymbolAddress((void**)&p_x1, g_x1);   cudaGetSymbolAddress((void**)&p_x2, g_x2);
    cudaGetSymbolAddress((void**)&p_h1, g_h1);   cudaGetSymbolAddress((void**)&p_h3, g_h3);
    cudaGetSymbolAddress((void**)&p_y, g_y);
    cudaGetSymbolAddress((void**)&p_xh, g_xh);   cudaGetSymbolAddress((void**)&p_xl, g_xl);
    cudaGetSymbolAddress((void**)&p_ath, g_ath); cudaGetSymbolAddress((void**)&p_atl, g_atl);
    cudaGetSymbolAddress((void**)&p_x2h, g_x2h); cudaGetSymbolAddress((void**)&p_x2l, g_x2l);
    cudaGetSymbolAddress((void**)&p_x3h, g_x3h); cudaGetSymbolAddress((void**)&p_x3l, g_x3l);
    cudaGetSymbolAddress((void**)&p_hh, g_hh);   cudaGetSymbolAddress((void**)&p_hl, g_hl);
    cudaGetSymbolAddress((void**)&p_wqkvh, g_wqkvh); cudaGetSymbolAddress((void**)&p_wqkvl, g_wqkvl);
    cudaGetSymbolAddress((void**)&p_woh, g_woh); cudaGetSymbolAddress((void**)&p_wol, g_wol);
    cudaGetSymbolAddress((void**)&p_w1h, g_w1h); cudaGetSymbolAddress((void**)&p_w1l, g_w1l);
    cudaGetSymbolAddress((void**)&p_w3h, g_w3h); cudaGetSymbolAddress((void**)&p_w3l, g_w3l);
    cudaGetSymbolAddress((void**)&p_w2h, g_w2h); cudaGetSymbolAddress((void**)&p_w2l, g_w2l);
    cudaGetSymbolAddress((void**)&p_hwh, g_hwh); cudaGetSymbolAddress((void**)&p_hwl, g_hwl);
    cudaGetSymbolAddress((void**)&p_etok, g_etok);

    const int CVB = 592, CVT = 256;
    cvt_split_k<<<CVB, CVT>>>((const float4*)wq, p_wqkvh,           p_wqkvl,           (long)DM*DM/4);
    cvt_split_k<<<CVB, CVT>>>((const float4*)wk, p_wqkvh + DM*DM,   p_wqkvl + DM*DM,   (long)DM*DM/4);
    cvt_split_k<<<CVB, CVT>>>((const float4*)wv, p_wqkvh + 2*DM*DM, p_wqkvl + 2*DM*DM, (long)DM*DM/4);
    cvt_split_k<<<CVB, CVT>>>((const float4*)wo, p_woh, p_wol, (long)DM*DM/4);
    cvt_split_k<<<CVB, CVT>>>((const float4*)w1, p_w1h, p_w1l, (long)NE*DF*DM/4);
    cvt_split_k<<<CVB, CVT>>>((const float4*)w3, p_w3h, p_w3l, (long)NE*DF*DM/4);
    cvt_split_k<<<CVB, CVT>>>((const float4*)w2, p_w2h, p_w2l, (long)NE*DM*DF/4);
    cvt_split_k<<<CVB, CVT>>>((const float4*)head_w, p_hwh, p_hwl, (long)VOC*DM/4);

    ropetab_k<<<SQ, 32>>>();
    embed_k<<<SQ, 256>>>(tokens, emb);

    // fused QKV: [1024 x 6144]
    mma_gemm<<<dim3(8, QKVN/128, 1), 256, GSMEM_BYTES>>>(p_xh, p_xl, p_wqkvh, p_wqkvl,
        p_qkv, nullptr, nullptr, SQ, QKVN, DM, QKVN, 0, 0, 0);

    rope_k<<<SQ, 1024>>>();
    attn_k<<<dim3(NH, NBLK), 256>>>();

    // O-proj + residual
    mma_gemm<<<dim3(8, DM/128, 1), 256, GSMEM_BYTES>>>(p_ath, p_atl, p_woh, p_wol,
        p_x1, p_x, nullptr, SQ, DM, DM, DM, 0, 0, 0);
    layernorm_k<<<SQ, 256>>>(p_x1, ln1_g, ln1_b, p_x2, p_x2h, p_x2l);

    init_moe_k<<<1, 32>>>();
    gate_k<<<SQ, 128>>>(p_x2, gate_w);

    // MoE
    mma_gemm<<<dim3(8, DF/128, NE), 256, GSMEM_BYTES>>>(p_x2h, p_x2l, p_w1h, p_w1l,
        p_h1, nullptr, p_etok, -1, DF, DM, DF, 0, (long)DF*DM, (long)SQ*DF);
    mma_gemm<<<dim3(8, DF/128, NE), 256, GSMEM_BYTES>>>(p_x2h, p_x2l, p_w3h, p_w3l,
        p_h3, nullptr, p_etok, -1, DF, DM, DF, 0, (long)DF*DM, (long)SQ*DF);
    silu_split_k<<<NE * SQ, 256>>>();
    mma_gemm<<<dim3(8, DM/128, NE), 256, GSMEM_BYTES>>>(p_hh, p_hl, p_w2h, p_w2l,
        p_y, nullptr, nullptr, -1, DM, DF, DM, (long)SQ*DF, (long)DM*DF, (long)SQ*DM);

    combine_ln_k<<<SQ, 256>>>(p_y, p_x2, ln2_g, ln2_b, fin_g, fin_b);

    // head
    mma_gemm<<<dim3(8, (VOC + 127)/128, 1), 256, GSMEM_BYTES>>>(p_x3h, p_x3l, p_hwh, p_hwl,
        out, nullptr, nullptr, SQ, VOC, DM, VOC, 0, 0, 0);
    aux_write_k<<<1, 1>>>(out, out_size);
}